// round 1
// baseline (speedup 1.0000x reference)
#include <cuda_runtime.h>

#define SEQ_L  16384
#define DIM_I  2048
#define DIM_N  2048
#define CHUNK  128
#define NCHUNK (SEQ_L / CHUNK)

// Scratch (device globals — no allocation allowed in kernel_launch)
__device__ float g_B  [(size_t)SEQ_L  * DIM_N];   // xs @ w_in^T
__device__ float g_H  [(size_t)SEQ_L  * DIM_N];   // scan output
__device__ float g_E  [(size_t)NCHUNK * DIM_N];   // per-chunk local-scan tails
__device__ float g_Cin[(size_t)NCHUNK * DIM_N];   // per-chunk carry-in

// ---------------------------------------------------------------------------
// GEMM (NT): C[M,Nn] = A[M,K] * B[Nn,K]^T   (both row-major, K contiguous)
// 128x128 block tile, BK=16, 256 threads, 8x8 per thread, double-buffered smem.
// FUSE_SKIP adds xs[m,n]*d_skip[n] in the epilogue (GEMM2 only).
// Dims are exact multiples of the tiles (16384, 2048, 2048) — no bounds checks.
// ---------------------------------------------------------------------------
template<bool FUSE_SKIP>
__global__ void __launch_bounds__(256, 2)
gemm_nt_kernel(const float* __restrict__ A, const float* __restrict__ B,
               float* __restrict__ C,
               const float* __restrict__ sx, const float* __restrict__ sd,
               int M, int Nn, int K)
{
    __shared__ float As[2][16][132];
    __shared__ float Bs[2][16][132];

    const int tid  = threadIdx.x;
    const int m0   = blockIdx.y * 128;
    const int n0   = blockIdx.x * 128;
    const int lrow = tid >> 2;           // 0..63 (row within tile; +64 for 2nd half)
    const int lk   = (tid & 3) << 2;     // 0,4,8,12 (k offset within BK)

    const float* Ag = A + (size_t)(m0 + lrow) * K + lk;
    const float* Bg = B + (size_t)(n0 + lrow) * K + lk;
    const size_t rstep = (size_t)64 * K;

    float4 ra0, ra1, rb0, rb1;

#define SSTORE(buf) do {                                                       \
    As[buf][lk+0][lrow]    = ra0.x; As[buf][lk+1][lrow]    = ra0.y;            \
    As[buf][lk+2][lrow]    = ra0.z; As[buf][lk+3][lrow]    = ra0.w;            \
    As[buf][lk+0][lrow+64] = ra1.x; As[buf][lk+1][lrow+64] = ra1.y;            \
    As[buf][lk+2][lrow+64] = ra1.z; As[buf][lk+3][lrow+64] = ra1.w;            \
    Bs[buf][lk+0][lrow]    = rb0.x; Bs[buf][lk+1][lrow]    = rb0.y;            \
    Bs[buf][lk+2][lrow]    = rb0.z; Bs[buf][lk+3][lrow]    = rb0.w;            \
    Bs[buf][lk+0][lrow+64] = rb1.x; Bs[buf][lk+1][lrow+64] = rb1.y;            \
    Bs[buf][lk+2][lrow+64] = rb1.z; Bs[buf][lk+3][lrow+64] = rb1.w;            \
  } while (0)

    // prologue: tile 0
    ra0 = *(const float4*)(Ag);
    ra1 = *(const float4*)(Ag + rstep);
    rb0 = *(const float4*)(Bg);
    rb1 = *(const float4*)(Bg + rstep);
    SSTORE(0);
    __syncthreads();

    const int ty = tid >> 4;   // 0..15
    const int tx = tid & 15;   // 0..15

    float acc[8][8];
    #pragma unroll
    for (int i = 0; i < 8; ++i)
        #pragma unroll
        for (int j = 0; j < 8; ++j) acc[i][j] = 0.f;

    const int ktiles = K >> 4;
    for (int kt = 0; kt < ktiles; ++kt) {
        const int buf = kt & 1;
        if (kt + 1 < ktiles) {
            const float* pa = Ag + (size_t)(kt + 1) * 16;
            const float* pb = Bg + (size_t)(kt + 1) * 16;
            ra0 = *(const float4*)(pa);
            ra1 = *(const float4*)(pa + rstep);
            rb0 = *(const float4*)(pb);
            rb1 = *(const float4*)(pb + rstep);
        }
        #pragma unroll
        for (int k = 0; k < 16; ++k) {
            float a[8], b[8];
            *(float4*)&a[0] = *(const float4*)&As[buf][k][ty * 4];
            *(float4*)&a[4] = *(const float4*)&As[buf][k][64 + ty * 4];
            *(float4*)&b[0] = *(const float4*)&Bs[buf][k][tx * 4];
            *(float4*)&b[4] = *(const float4*)&Bs[buf][k][64 + tx * 4];
            #pragma unroll
            for (int i = 0; i < 8; ++i)
                #pragma unroll
                for (int j = 0; j < 8; ++j)
                    acc[i][j] = fmaf(a[i], b[j], acc[i][j]);
        }
        if (kt + 1 < ktiles) {
            SSTORE(buf ^ 1);
            __syncthreads();
        }
    }
#undef SSTORE

    // epilogue
    #pragma unroll
    for (int i = 0; i < 8; ++i) {
        const int mrow = m0 + ((i < 4) ? (ty * 4 + i) : (64 + ty * 4 + (i - 4)));
        float* crow = C + (size_t)mrow * Nn;
        const int c0 = n0 + tx * 4;
        const int c1 = n0 + 64 + tx * 4;
        float4 v0 = make_float4(acc[i][0], acc[i][1], acc[i][2], acc[i][3]);
        float4 v1 = make_float4(acc[i][4], acc[i][5], acc[i][6], acc[i][7]);
        if (FUSE_SKIP) {
            const float* xrow = sx + (size_t)mrow * Nn;
            v0.x = fmaf(xrow[c0 + 0], sd[c0 + 0], v0.x);
            v0.y = fmaf(xrow[c0 + 1], sd[c0 + 1], v0.y);
            v0.z = fmaf(xrow[c0 + 2], sd[c0 + 2], v0.z);
            v0.w = fmaf(xrow[c0 + 3], sd[c0 + 3], v0.w);
            v1.x = fmaf(xrow[c1 + 0], sd[c1 + 0], v1.x);
            v1.y = fmaf(xrow[c1 + 1], sd[c1 + 1], v1.y);
            v1.z = fmaf(xrow[c1 + 2], sd[c1 + 2], v1.z);
            v1.w = fmaf(xrow[c1 + 3], sd[c1 + 3], v1.w);
        }
        *(float4*)(crow + c0) = v0;
        *(float4*)(crow + c1) = v1;
    }
}

// ---------------------------------------------------------------------------
// Chunked diagonal scan: h_t = lam * h_{t-1} + b_t  (per state column n)
// Phase 1: per-(chunk, state) local scan tail (carry-in 0)
// Phase 2: per-state serial combine across NCHUNK chunks (carry-ins)
// Phase 3: per-(chunk, state) apply with carry-in, write H
// ---------------------------------------------------------------------------
__global__ void scan_chunk_reduce(const float* __restrict__ Bmat,
                                  const float* __restrict__ lam,
                                  float* __restrict__ E)
{
    const int n = blockIdx.x * blockDim.x + threadIdx.x;
    const int c = blockIdx.y;
    const float l = lam[n];
    const float* p = Bmat + (size_t)c * CHUNK * DIM_N + n;
    float h = 0.f;
    #pragma unroll 4
    for (int t = 0; t < CHUNK; ++t)
        h = fmaf(l, h, p[(size_t)t * DIM_N]);
    E[(size_t)c * DIM_N + n] = h;
}

__global__ void scan_carry(const float* __restrict__ lam,
                           const float* __restrict__ E,
                           float* __restrict__ Cin)
{
    const int n = blockIdx.x * blockDim.x + threadIdx.x;
    const float l = lam[n];
    float lT = l;
    #pragma unroll
    for (int i = 0; i < 7; ++i) lT *= lT;   // l^128 by repeated squaring
    float cin = 0.f;
    for (int c = 0; c < NCHUNK; ++c) {
        Cin[(size_t)c * DIM_N + n] = cin;
        cin = fmaf(lT, cin, E[(size_t)c * DIM_N + n]);
    }
}

__global__ void scan_apply(const float* __restrict__ Bmat,
                           const float* __restrict__ lam,
                           const float* __restrict__ Cin,
                           float* __restrict__ H)
{
    const int n = blockIdx.x * blockDim.x + threadIdx.x;
    const int c = blockIdx.y;
    const float l = lam[n];
    const float* p = Bmat + (size_t)c * CHUNK * DIM_N + n;
    float*       q = H    + (size_t)c * CHUNK * DIM_N + n;
    float h = Cin[(size_t)c * DIM_N + n];
    #pragma unroll 4
    for (int t = 0; t < CHUNK; ++t) {
        h = fmaf(l, h, p[(size_t)t * DIM_N]);
        q[(size_t)t * DIM_N] = h;
    }
}

// ---------------------------------------------------------------------------
extern "C" void kernel_launch(void* const* d_in, const int* in_sizes, int n_in,
                              void* d_out, int out_size)
{
    const float* xs     = (const float*)d_in[0];   // [SEQ_L, DIM_I]
    const float* lam    = (const float*)d_in[1];   // [DIM_N]
    const float* w_in   = (const float*)d_in[2];   // [DIM_N, DIM_I]
    const float* c_out  = (const float*)d_in[3];   // [DIM_I, DIM_N]
    const float* d_skip = (const float*)d_in[4];   // [DIM_I]
    float* out = (float*)d_out;                    // [SEQ_L, DIM_I]

    float *Bp, *Hp, *Ep, *Cp;
    cudaGetSymbolAddress((void**)&Bp, g_B);
    cudaGetSymbolAddress((void**)&Hp, g_H);
    cudaGetSymbolAddress((void**)&Ep, g_E);
    cudaGetSymbolAddress((void**)&Cp, g_Cin);

    // GEMM1: B = xs @ w_in^T   [SEQ_L, DIM_N]
    dim3 g1(DIM_N / 128, SEQ_L / 128);
    gemm_nt_kernel<false><<<g1, 256>>>(xs, w_in, Bp, nullptr, nullptr,
                                       SEQ_L, DIM_N, DIM_I);

    // Scan: H = assoc_scan(lam, B)
    dim3 gs(DIM_N / 256, NCHUNK);
    scan_chunk_reduce<<<gs, 256>>>(Bp, lam, Ep);
    scan_carry<<<DIM_N / 256, 256>>>(lam, Ep, Cp);
    scan_apply<<<gs, 256>>>(Bp, lam, Cp, Hp);

    // GEMM2: out = H @ c_out^T + xs * d_skip   [SEQ_L, DIM_I]
    dim3 g2(DIM_I / 128, SEQ_L / 128);
    gemm_nt_kernel<true><<<g2, 256>>>(Hp, c_out, out, xs, d_skip,
                                      SEQ_L, DIM_I, DIM_N);
}

// round 2
// speedup vs baseline: 2.6676x; 2.6676x over previous
#include <cuda_runtime.h>
#include <cstdint>

#define SEQ_L  16384
#define DIM_I  2048
#define DIM_N  2048
#define CHUNK  128
#define NCHUNK (SEQ_L / CHUNK)

// Scratch (device globals — no allocation allowed in kernel_launch)
__device__ float g_B  [(size_t)SEQ_L  * DIM_N];
__device__ float g_H  [(size_t)SEQ_L  * DIM_N];
__device__ float g_E  [(size_t)NCHUNK * DIM_N];
__device__ float g_Cin[(size_t)NCHUNK * DIM_N];

__device__ __forceinline__ uint32_t f2tf32(float f) {
    uint32_t u;
    asm("cvt.rna.tf32.f32 %0, %1;" : "=r"(u) : "f"(f));
    return u;
}

// ---------------------------------------------------------------------------
// Tensor-core GEMM (NT): C[M,Nn] = A[M,K] * B[Nn,K]^T, fp32 in, tf32 mma.
// CTA tile 128x128, BK=16, 128 threads = 4 warps (2x2), warp tile 64x64.
// mma.sync.m16n8k8 tf32. Smem row stride 20 (pad 4) => the fragment access
// pattern (bank = (g*20 + c) mod 32 = perm of 0..31) is conflict-free.
// ---------------------------------------------------------------------------
template<bool FUSE_SKIP>
__global__ void __launch_bounds__(128)
gemm_tc(const float* __restrict__ A, const float* __restrict__ B,
        float* __restrict__ C,
        const float* __restrict__ sx, const float* __restrict__ sd,
        int M, int Nn, int K)
{
    constexpr int BM = 128, BN = 128, BK = 16, LDSM = 20;
    __shared__ uint32_t As[2][BM * LDSM];
    __shared__ uint32_t Bs[2][BN * LDSM];

    const int tid    = threadIdx.x;
    const int lane   = tid & 31;
    const int wid    = tid >> 5;
    const int warp_m = wid & 1;       // 0..1
    const int warp_n = wid >> 1;      // 0..1
    const int g      = lane >> 2;     // groupID 0..7
    const int c      = lane & 3;      // threadID_in_group 0..3

    const int m0 = blockIdx.y * BM;
    const int n0 = blockIdx.x * BN;

    // gmem load mapping: thread covers rows lrow, lrow+32, lrow+64, lrow+96,
    // one float4 (4 consecutive k) each, per matrix.
    const int lrow = tid >> 2;
    const int lc4  = (tid & 3) * 4;
    const float* Ag = A + (size_t)(m0 + lrow) * K + lc4;
    const float* Bg = B + (size_t)(n0 + lrow) * K + lc4;
    const size_t rstep = (size_t)32 * K;

    float4 ra[4], rb[4];

#define LDG_TILE(kt) do {                                                   \
    const float* pa = Ag + (size_t)(kt) * BK;                               \
    const float* pb = Bg + (size_t)(kt) * BK;                               \
    ra[0] = *(const float4*)(pa);                                           \
    ra[1] = *(const float4*)(pa + rstep);                                   \
    ra[2] = *(const float4*)(pa + 2 * rstep);                               \
    ra[3] = *(const float4*)(pa + 3 * rstep);                               \
    rb[0] = *(const float4*)(pb);                                           \
    rb[1] = *(const float4*)(pb + rstep);                                   \
    rb[2] = *(const float4*)(pb + 2 * rstep);                               \
    rb[3] = *(const float4*)(pb + 3 * rstep);                               \
  } while (0)

#define STS_TILE(buf) do {                                                  \
    _Pragma("unroll")                                                       \
    for (int i = 0; i < 4; ++i) {                                           \
        const int off = (lrow + i * 32) * LDSM + lc4;                       \
        uint4 va, vb;                                                       \
        va.x = f2tf32(ra[i].x); va.y = f2tf32(ra[i].y);                     \
        va.z = f2tf32(ra[i].z); va.w = f2tf32(ra[i].w);                     \
        vb.x = f2tf32(rb[i].x); vb.y = f2tf32(rb[i].y);                     \
        vb.z = f2tf32(rb[i].z); vb.w = f2tf32(rb[i].w);                     \
        *(uint4*)&As[buf][off] = va;                                        \
        *(uint4*)&Bs[buf][off] = vb;                                        \
    }                                                                       \
  } while (0)

    float acc[4][8][4];
    #pragma unroll
    for (int mt = 0; mt < 4; ++mt)
        #pragma unroll
        for (int nt = 0; nt < 8; ++nt)
            #pragma unroll
            for (int r = 0; r < 4; ++r) acc[mt][nt][r] = 0.f;

    LDG_TILE(0);
    STS_TILE(0);
    __syncthreads();

    const int KT = K / BK;   // 128
    for (int kt = 0; kt < KT; ++kt) {
        const int buf = kt & 1;
        if (kt + 1 < KT) LDG_TILE(kt + 1);

        #pragma unroll
        for (int kc = 0; kc < BK / 8; ++kc) {
            uint32_t af[4][4], bf[8][2];
            #pragma unroll
            for (int mt = 0; mt < 4; ++mt) {
                const int base = (warp_m * 64 + mt * 16 + g) * LDSM + kc * 8 + c;
                af[mt][0] = As[buf][base];
                af[mt][1] = As[buf][base + 8 * LDSM];
                af[mt][2] = As[buf][base + 4];
                af[mt][3] = As[buf][base + 8 * LDSM + 4];
            }
            #pragma unroll
            for (int nt = 0; nt < 8; ++nt) {
                const int base = (warp_n * 64 + nt * 8 + g) * LDSM + kc * 8 + c;
                bf[nt][0] = Bs[buf][base];
                bf[nt][1] = Bs[buf][base + 4];
            }
            #pragma unroll
            for (int mt = 0; mt < 4; ++mt)
                #pragma unroll
                for (int nt = 0; nt < 8; ++nt) {
                    asm volatile(
                        "mma.sync.aligned.m16n8k8.row.col.f32.tf32.tf32.f32 "
                        "{%0,%1,%2,%3}, {%4,%5,%6,%7}, {%8,%9}, {%0,%1,%2,%3};"
                        : "+f"(acc[mt][nt][0]), "+f"(acc[mt][nt][1]),
                          "+f"(acc[mt][nt][2]), "+f"(acc[mt][nt][3])
                        : "r"(af[mt][0]), "r"(af[mt][1]),
                          "r"(af[mt][2]), "r"(af[mt][3]),
                          "r"(bf[nt][0]), "r"(bf[nt][1]));
                }
        }

        if (kt + 1 < KT) {
            STS_TILE(buf ^ 1);
            __syncthreads();
        }
    }
#undef LDG_TILE
#undef STS_TILE

    // epilogue: c0:(g, 2c) c1:(g, 2c+1) c2:(g+8, 2c) c3:(g+8, 2c+1)
    #pragma unroll
    for (int mt = 0; mt < 4; ++mt) {
        const int r0 = m0 + warp_m * 64 + mt * 16 + g;
        const int r1 = r0 + 8;
        float* p0 = C + (size_t)r0 * Nn;
        float* p1 = C + (size_t)r1 * Nn;
        #pragma unroll
        for (int nt = 0; nt < 8; ++nt) {
            const int col = n0 + warp_n * 64 + nt * 8 + c * 2;
            float2 v0 = make_float2(acc[mt][nt][0], acc[mt][nt][1]);
            float2 v1 = make_float2(acc[mt][nt][2], acc[mt][nt][3]);
            if (FUSE_SKIP) {
                const float2 x0 = *(const float2*)(sx + (size_t)r0 * Nn + col);
                const float2 x1 = *(const float2*)(sx + (size_t)r1 * Nn + col);
                const float2 dd = *(const float2*)(sd + col);
                v0.x = fmaf(x0.x, dd.x, v0.x);
                v0.y = fmaf(x0.y, dd.y, v0.y);
                v1.x = fmaf(x1.x, dd.x, v1.x);
                v1.y = fmaf(x1.y, dd.y, v1.y);
            }
            *(float2*)(p0 + col) = v0;
            *(float2*)(p1 + col) = v1;
        }
    }
}

// ---------------------------------------------------------------------------
// Chunked diagonal scan: h_t = lam * h_{t-1} + b_t  (per state column n)
// ---------------------------------------------------------------------------
__global__ void scan_chunk_reduce(const float* __restrict__ Bmat,
                                  const float* __restrict__ lam,
                                  float* __restrict__ E)
{
    const int n = blockIdx.x * blockDim.x + threadIdx.x;
    const int cc = blockIdx.y;
    const float l = lam[n];
    const float* p = Bmat + (size_t)cc * CHUNK * DIM_N + n;
    float h = 0.f;
    #pragma unroll 4
    for (int t = 0; t < CHUNK; ++t)
        h = fmaf(l, h, p[(size_t)t * DIM_N]);
    E[(size_t)cc * DIM_N + n] = h;
}

__global__ void scan_carry(const float* __restrict__ lam,
                           const float* __restrict__ E,
                           float* __restrict__ Cin)
{
    const int n = blockIdx.x * blockDim.x + threadIdx.x;
    const float l = lam[n];
    float lT = l;
    #pragma unroll
    for (int i = 0; i < 7; ++i) lT *= lT;   // l^128
    float cin = 0.f;
    for (int cc = 0; cc < NCHUNK; ++cc) {
        Cin[(size_t)cc * DIM_N + n] = cin;
        cin = fmaf(lT, cin, E[(size_t)cc * DIM_N + n]);
    }
}

__global__ void scan_apply(const float* __restrict__ Bmat,
                           const float* __restrict__ lam,
                           const float* __restrict__ Cin,
                           float* __restrict__ H)
{
    const int n = blockIdx.x * blockDim.x + threadIdx.x;
    const int cc = blockIdx.y;
    const float l = lam[n];
    const float* p = Bmat + (size_t)cc * CHUNK * DIM_N + n;
    float*       q = H    + (size_t)cc * CHUNK * DIM_N + n;
    float h = Cin[(size_t)cc * DIM_N + n];
    #pragma unroll 4
    for (int t = 0; t < CHUNK; ++t) {
        h = fmaf(l, h, p[(size_t)t * DIM_N]);
        q[(size_t)t * DIM_N] = h;
    }
}

// ---------------------------------------------------------------------------
extern "C" void kernel_launch(void* const* d_in, const int* in_sizes, int n_in,
                              void* d_out, int out_size)
{
    const float* xs     = (const float*)d_in[0];   // [SEQ_L, DIM_I]
    const float* lam    = (const float*)d_in[1];   // [DIM_N]
    const float* w_in   = (const float*)d_in[2];   // [DIM_N, DIM_I]
    const float* c_out  = (const float*)d_in[3];   // [DIM_I, DIM_N]
    const float* d_skip = (const float*)d_in[4];   // [DIM_I]
    float* out = (float*)d_out;                    // [SEQ_L, DIM_I]

    float *Bp, *Hp, *Ep, *Cp;
    cudaGetSymbolAddress((void**)&Bp, g_B);
    cudaGetSymbolAddress((void**)&Hp, g_H);
    cudaGetSymbolAddress((void**)&Ep, g_E);
    cudaGetSymbolAddress((void**)&Cp, g_Cin);

    // GEMM1: B = xs @ w_in^T
    dim3 g1(DIM_N / 128, SEQ_L / 128);
    gemm_tc<false><<<g1, 128>>>(xs, w_in, Bp, nullptr, nullptr,
                                SEQ_L, DIM_N, DIM_I);

    // Scan: H = assoc_scan(lam, B)
    dim3 gs(DIM_N / 256, NCHUNK);
    scan_chunk_reduce<<<gs, 256>>>(Bp, lam, Ep);
    scan_carry<<<DIM_N / 256, 256>>>(lam, Ep, Cp);
    scan_apply<<<gs, 256>>>(Bp, lam, Cp, Hp);

    // GEMM2: out = H @ c_out^T + xs * d_skip
    dim3 g2(DIM_I / 128, SEQ_L / 128);
    gemm_tc<true><<<g2, 128>>>(Hp, c_out, out, xs, d_skip,
                               SEQ_L, DIM_I, DIM_N);
}

// round 4
// speedup vs baseline: 3.4186x; 1.2815x over previous
#include <cuda_runtime.h>
#include <cstdint>

#define SEQ_L  16384
#define DIM_I  2048
#define DIM_N  2048
#define CHUNK  128
#define NCHUNK (SEQ_L / CHUNK)

// Scratch (device globals — no allocation allowed in kernel_launch)
__device__ float g_B  [(size_t)SEQ_L  * DIM_N];
__device__ float g_H  [(size_t)SEQ_L  * DIM_N];   // tf32-rounded by scan_apply
__device__ float g_E  [(size_t)NCHUNK * DIM_N];
__device__ float g_Cin[(size_t)NCHUNK * DIM_N];
__device__ float g_Xc [(size_t)SEQ_L  * DIM_I];   // rna(xs)
__device__ float g_Wc [(size_t)DIM_N  * DIM_I];   // rna(w_in)
__device__ float g_Cc [(size_t)DIM_I  * DIM_N];   // rna(c_out)

__device__ __forceinline__ uint32_t f2tf32(float f) {
    uint32_t u;
    asm("cvt.rna.tf32.f32 %0, %1;" : "=r"(u) : "f"(f));
    return u;
}
__device__ __forceinline__ uint32_t smem_u32(const void* p) {
    uint32_t a;
    asm("{ .reg .u64 t; cvta.to.shared.u64 t, %1; cvt.u32.u64 %0, t; }"
        : "=r"(a) : "l"(p));
    return a;
}

// ---------------------------------------------------------------------------
// One-time tf32 rounding of GEMM operands (element count divisible by 4)
// ---------------------------------------------------------------------------
__global__ void cvt_tf32_kernel(const float4* __restrict__ in,
                                float4* __restrict__ out, int n4)
{
    int i = blockIdx.x * blockDim.x + threadIdx.x;
    if (i < n4) {
        float4 v = in[i];
        float4 o;
        o.x = __uint_as_float(f2tf32(v.x));
        o.y = __uint_as_float(f2tf32(v.y));
        o.z = __uint_as_float(f2tf32(v.z));
        o.w = __uint_as_float(f2tf32(v.w));
        out[i] = o;
    }
}

// ---------------------------------------------------------------------------
// tf32 mma.sync GEMM (NT): C[M,Nn] = A[M,K]*B[Nn,K]^T. A,B already tf32-rounded.
// CTA 128x128, BK=32, 256 thr = 8 warps (2x4), warp tile 64x32.
// 3-stage cp.async.cg pipeline, XOR-swizzled smem (conflict-free).
// ---------------------------------------------------------------------------
template<bool FUSE_SKIP>
__global__ void __launch_bounds__(256, 2)
gemm_mma(const float* __restrict__ A, const float* __restrict__ Bm,
         float* __restrict__ C, const float* __restrict__ sx,
         const float* __restrict__ sd, int M, int Nn, int K)
{
    constexpr int BK = 32, STAGES = 3;
    // stage layout (uint32 words): A tile 128*32=4096 words, B tile 4096 words
    extern __shared__ uint32_t smp[];

    const int tid    = threadIdx.x;
    const int lane   = tid & 31;
    const int wid    = tid >> 5;
    const int warp_m = wid & 1;        // 0..1  (64 rows)
    const int warp_n = wid >> 1;       // 0..3  (32 cols)
    const int g      = lane >> 2;      // 0..7
    const int c      = lane & 3;       // 0..3

    const int m0 = blockIdx.y * 128;
    const int n0 = blockIdx.x * 128;

    // ---- cp.async fill mapping: thread -> rows (tid>>3)+{0,32,64,96}, unit tid&7
    const int frow = tid >> 3;         // 0..31
    const int fu   = tid & 7;          // 16B unit within 128B row
    const int r7   = frow & 7;
    const float* Ag = A  + (size_t)(m0 + frow) * K + fu * 4;
    const float* Bg = Bm + (size_t)(n0 + frow) * K + fu * 4;
    const size_t rstep = (size_t)32 * K;

    const uint32_t sbw = smem_u32(smp);
    uint32_t dsto[4];
    #pragma unroll
    for (int i = 0; i < 4; ++i)
        dsto[i] = (uint32_t)(frow + i * 32) * 128u + (uint32_t)((fu ^ r7) << 4);

#define ISSUE_STAGE(st, kt) do {                                              \
    const uint32_t base = sbw + (uint32_t)(st) * 32768u;                      \
    const float* pa = Ag + (size_t)(kt) * BK;                                 \
    const float* pb = Bg + (size_t)(kt) * BK;                                 \
    _Pragma("unroll")                                                         \
    for (int i = 0; i < 4; ++i) {                                             \
        asm volatile("cp.async.cg.shared.global [%0], [%1], 16;"              \
            :: "r"(base + dsto[i]), "l"(pa + i * rstep) : "memory");          \
        asm volatile("cp.async.cg.shared.global [%0], [%1], 16;"              \
            :: "r"(base + 16384u + dsto[i]), "l"(pb + i * rstep) : "memory"); \
    }                                                                         \
    asm volatile("cp.async.commit_group;" ::: "memory");                      \
  } while (0)

    // ---- fragment smem word offsets (swizzle term reduces to u^g)
    uint32_t arow[4], brow[4];
    #pragma unroll
    for (int mt = 0; mt < 4; ++mt)
        arow[mt] = (uint32_t)(warp_m * 64 + mt * 16 + g) * 32u;
    #pragma unroll
    for (int nt = 0; nt < 4; ++nt)
        brow[nt] = (uint32_t)(warp_n * 32 + nt * 8 + g) * 32u;

    float acc[4][4][4];
    #pragma unroll
    for (int mt = 0; mt < 4; ++mt)
        #pragma unroll
        for (int nt = 0; nt < 4; ++nt)
            #pragma unroll
            for (int r = 0; r < 4; ++r) acc[mt][nt][r] = 0.f;

    const int KT = K / BK;   // 64

    ISSUE_STAGE(0, 0);
    ISSUE_STAGE(1, 1);

    for (int kt = 0; kt < KT; ++kt) {
        asm volatile("cp.async.wait_group 1;" ::: "memory");
        __syncthreads();
        if (kt + 2 < KT) {
            int st = kt + 2; st -= (st >= STAGES) ? STAGES : 0;
            st -= (st >= STAGES) ? STAGES : 0;
            ISSUE_STAGE((kt + 2) % STAGES, kt + 2);
        }

        const uint32_t* sA = smp + (kt % STAGES) * 8192;
        const uint32_t* sB = sA + 4096;

        #pragma unroll
        for (int kc = 0; kc < 4; ++kc) {
            const uint32_t x0 = (uint32_t)(((2 * kc)     ^ g) * 4 + c);
            const uint32_t x1 = (uint32_t)(((2 * kc + 1) ^ g) * 4 + c);
            uint32_t af[4][4], bf[4][2];
            #pragma unroll
            for (int mt = 0; mt < 4; ++mt) {
                af[mt][0] = sA[arow[mt] + x0];
                af[mt][1] = sA[arow[mt] + 256 + x0];
                af[mt][2] = sA[arow[mt] + x1];
                af[mt][3] = sA[arow[mt] + 256 + x1];
            }
            #pragma unroll
            for (int nt = 0; nt < 4; ++nt) {
                bf[nt][0] = sB[brow[nt] + x0];
                bf[nt][1] = sB[brow[nt] + x1];
            }
            #pragma unroll
            for (int mt = 0; mt < 4; ++mt)
                #pragma unroll
                for (int nt = 0; nt < 4; ++nt) {
                    asm volatile(
                        "mma.sync.aligned.m16n8k8.row.col.f32.tf32.tf32.f32 "
                        "{%0,%1,%2,%3}, {%4,%5,%6,%7}, {%8,%9}, {%0,%1,%2,%3};"
                        : "+f"(acc[mt][nt][0]), "+f"(acc[mt][nt][1]),
                          "+f"(acc[mt][nt][2]), "+f"(acc[mt][nt][3])
                        : "r"(af[mt][0]), "r"(af[mt][1]),
                          "r"(af[mt][2]), "r"(af[mt][3]),
                          "r"(bf[nt][0]), "r"(bf[nt][1]));
                }
        }
    }
#undef ISSUE_STAGE

    // epilogue: c0:(g,2c) c1:(g,2c+1) c2:(g+8,2c) c3:(g+8,2c+1)
    #pragma unroll
    for (int mt = 0; mt < 4; ++mt) {
        const int r0 = m0 + warp_m * 64 + mt * 16 + g;
        const int r1 = r0 + 8;
        float* p0 = C + (size_t)r0 * Nn;
        float* p1 = C + (size_t)r1 * Nn;
        #pragma unroll
        for (int nt = 0; nt < 4; ++nt) {
            const int col = n0 + warp_n * 32 + nt * 8 + c * 2;
            float2 v0 = make_float2(acc[mt][nt][0], acc[mt][nt][1]);
            float2 v1 = make_float2(acc[mt][nt][2], acc[mt][nt][3]);
            if (FUSE_SKIP) {
                const float2 x0 = *(const float2*)(sx + (size_t)r0 * Nn + col);
                const float2 x1 = *(const float2*)(sx + (size_t)r1 * Nn + col);
                const float2 dd = *(const float2*)(sd + col);
                v0.x = fmaf(x0.x, dd.x, v0.x);
                v0.y = fmaf(x0.y, dd.y, v0.y);
                v1.x = fmaf(x1.x, dd.x, v1.x);
                v1.y = fmaf(x1.y, dd.y, v1.y);
            }
            *(float2*)(p0 + col) = v0;
            *(float2*)(p1 + col) = v1;
        }
    }
}

// ---------------------------------------------------------------------------
// Chunked diagonal scan: h_t = lam * h_{t-1} + b_t
// ---------------------------------------------------------------------------
__global__ void scan_chunk_reduce(const float* __restrict__ Bmat,
                                  const float* __restrict__ lam,
                                  float* __restrict__ E)
{
    const int n = blockIdx.x * blockDim.x + threadIdx.x;
    const int cc = blockIdx.y;
    const float l = lam[n];
    const float* p = Bmat + (size_t)cc * CHUNK * DIM_N + n;
    float h = 0.f;
    #pragma unroll 4
    for (int t = 0; t < CHUNK; ++t)
        h = fmaf(l, h, p[(size_t)t * DIM_N]);
    E[(size_t)cc * DIM_N + n] = h;
}

__global__ void scan_carry(const float* __restrict__ lam,
                           const float* __restrict__ E,
                           float* __restrict__ Cin)
{
    const int n = blockIdx.x * blockDim.x + threadIdx.x;
    const float l = lam[n];
    float lT = l;
    #pragma unroll
    for (int i = 0; i < 7; ++i) lT *= lT;   // l^128
    float cin = 0.f;
    for (int cc = 0; cc < NCHUNK; ++cc) {
        Cin[(size_t)cc * DIM_N + n] = cin;
        cin = fmaf(lT, cin, E[(size_t)cc * DIM_N + n]);
    }
}

// writes tf32-rounded H (it is consumed only as GEMM2's A operand)
__global__ void scan_apply(const float* __restrict__ Bmat,
                           const float* __restrict__ lam,
                           const float* __restrict__ Cin,
                           float* __restrict__ H)
{
    const int n = blockIdx.x * blockDim.x + threadIdx.x;
    const int cc = blockIdx.y;
    const float l = lam[n];
    const float* p = Bmat + (size_t)cc * CHUNK * DIM_N + n;
    float*       q = H    + (size_t)cc * CHUNK * DIM_N + n;
    float h = Cin[(size_t)cc * DIM_N + n];
    #pragma unroll 4
    for (int t = 0; t < CHUNK; ++t) {
        h = fmaf(l, h, p[(size_t)t * DIM_N]);
        q[(size_t)t * DIM_N] = __uint_as_float(f2tf32(h));
    }
}

// ---------------------------------------------------------------------------
extern "C" void kernel_launch(void* const* d_in, const int* in_sizes, int n_in,
                              void* d_out, int out_size)
{
    const float* xs     = (const float*)d_in[0];   // [SEQ_L, DIM_I]
    const float* lam    = (const float*)d_in[1];   // [DIM_N]
    const float* w_in   = (const float*)d_in[2];   // [DIM_N, DIM_I]
    const float* c_out  = (const float*)d_in[3];   // [DIM_I, DIM_N]
    const float* d_skip = (const float*)d_in[4];   // [DIM_I]
    float* out = (float*)d_out;                    // [SEQ_L, DIM_I]

    float *Bp, *Hp, *Ep, *Cp, *Xc, *Wc, *Cc;
    cudaGetSymbolAddress((void**)&Bp, g_B);
    cudaGetSymbolAddress((void**)&Hp, g_H);
    cudaGetSymbolAddress((void**)&Ep, g_E);
    cudaGetSymbolAddress((void**)&Cp, g_Cin);
    cudaGetSymbolAddress((void**)&Xc, g_Xc);
    cudaGetSymbolAddress((void**)&Wc, g_Wc);
    cudaGetSymbolAddress((void**)&Cc, g_Cc);

    const int SMEM_DYN = 3 * 32768;   // 96 KB
    cudaFuncSetAttribute(gemm_mma<false>,
        cudaFuncAttributeMaxDynamicSharedMemorySize, SMEM_DYN);
    cudaFuncSetAttribute(gemm_mma<true>,
        cudaFuncAttributeMaxDynamicSharedMemorySize, SMEM_DYN);

    // Pre-round operands to tf32
    {
        int n4 = SEQ_L * DIM_I / 4;
        cvt_tf32_kernel<<<n4 / 256, 256>>>((const float4*)xs, (float4*)Xc, n4);
        n4 = DIM_N * DIM_I / 4;
        cvt_tf32_kernel<<<n4 / 256, 256>>>((const float4*)w_in, (float4*)Wc, n4);
        n4 = DIM_I * DIM_N / 4;
        cvt_tf32_kernel<<<n4 / 256, 256>>>((const float4*)c_out, (float4*)Cc, n4);
    }

    // GEMM1: B = xs @ w_in^T
    dim3 g1(DIM_N / 128, SEQ_L / 128);
    gemm_mma<false><<<g1, 256, SMEM_DYN>>>(Xc, Wc, Bp, nullptr, nullptr,
                                           SEQ_L, DIM_N, DIM_I);

    // Scan: H = assoc_scan(lam, B)
    dim3 gs(DIM_N / 256, NCHUNK);
    scan_chunk_reduce<<<gs, 256>>>(Bp, lam, Ep);
    scan_carry<<<DIM_N / 256, 256>>>(lam, Ep, Cp);
    scan_apply<<<gs, 256>>>(Bp, lam, Cp, Hp);

    // GEMM2: out = H @ c_out^T + xs * d_skip
    dim3 g2(DIM_I / 128, SEQ_L / 128);
    gemm_mma<true><<<g2, 256, SMEM_DYN>>>(Hp, Cc, out, xs, d_skip,
                                          SEQ_L, DIM_I, DIM_N);
}

// round 5
// speedup vs baseline: 3.5823x; 1.0479x over previous
#include <cuda_runtime.h>
#include <cstdint>

#define SEQ_L  16384
#define DIM_I  2048
#define DIM_N  2048
#define CHUNK  128
#define NCHUNK (SEQ_L / CHUNK)

// Scratch (device globals — no allocation allowed in kernel_launch)
__device__ float g_B  [(size_t)SEQ_L  * DIM_N];
__device__ float g_H  [(size_t)SEQ_L  * DIM_N];   // tf32-rounded by scan_apply
__device__ float g_E  [(size_t)NCHUNK * DIM_N];
__device__ float g_Cin[(size_t)NCHUNK * DIM_N];
__device__ float g_Xc [(size_t)SEQ_L  * DIM_I];   // rna(xs)
__device__ float g_Wc [(size_t)DIM_N  * DIM_I];   // rna(w_in)
__device__ float g_Cc [(size_t)DIM_I  * DIM_N];   // rna(c_out)

__device__ __forceinline__ uint32_t f2tf32(float f) {
    uint32_t u;
    asm("cvt.rna.tf32.f32 %0, %1;" : "=r"(u) : "f"(f));
    return u;
}
__device__ __forceinline__ uint32_t smem_u32(const void* p) {
    uint32_t a;
    asm("{ .reg .u64 t; cvta.to.shared.u64 t, %1; cvt.u32.u64 %0, t; }"
        : "=r"(a) : "l"(p));
    return a;
}

// ---------------------------------------------------------------------------
// One-time tf32 rounding of GEMM operands
// ---------------------------------------------------------------------------
__global__ void cvt_tf32_kernel(const float4* __restrict__ in,
                                float4* __restrict__ out, int n4)
{
    int i = blockIdx.x * blockDim.x + threadIdx.x;
    if (i < n4) {
        float4 v = in[i];
        float4 o;
        o.x = __uint_as_float(f2tf32(v.x));
        o.y = __uint_as_float(f2tf32(v.y));
        o.z = __uint_as_float(f2tf32(v.z));
        o.w = __uint_as_float(f2tf32(v.w));
        out[i] = o;
    }
}

// ---------------------------------------------------------------------------
// tf32 mma.sync GEMM (NT): C[M,Nn] = A[M,K]*B[Nn,K]^T. A,B already tf32-rounded.
// CTA 128x128, BK=32, 128 thr = 4 warps (2x2), warp tile 64x64.
// 3-stage cp.async.cg pipeline, XOR-swizzled smem. 2 CTAs/SM (smem-bound),
// up to 255 regs/thread -> fragment double-buffering fits.
// ---------------------------------------------------------------------------
template<bool FUSE_SKIP>
__global__ void __launch_bounds__(128)
gemm_mma(const float* __restrict__ A, const float* __restrict__ Bm,
         float* __restrict__ C, const float* __restrict__ sx,
         const float* __restrict__ sd, int M, int Nn, int K)
{
    constexpr int BK = 32, STAGES = 3;
    extern __shared__ uint32_t smp[];   // per stage: A 4096 words, B 4096 words

    const int tid    = threadIdx.x;
    const int lane   = tid & 31;
    const int wid    = tid >> 5;
    const int warp_m = wid & 1;        // 0..1  (64 rows)
    const int warp_n = wid >> 1;       // 0..1  (64 cols)
    const int g      = lane >> 2;      // 0..7
    const int c      = lane & 3;       // 0..3

    const int m0 = blockIdx.y * 128;
    const int n0 = blockIdx.x * 128;

    // ---- cp.async fill: thread -> rows (tid>>3)+{0,16,...,112}, 16B unit tid&7
    const int frow = tid >> 3;         // 0..15
    const int fu   = tid & 7;
    const int r7   = frow & 7;
    const float* Ag = A  + (size_t)(m0 + frow) * K + fu * 4;
    const float* Bg = Bm + (size_t)(n0 + frow) * K + fu * 4;
    const size_t rstep = (size_t)16 * K;

    const uint32_t sbw = smem_u32(smp);
    uint32_t dsto[8];
    #pragma unroll
    for (int i = 0; i < 8; ++i)
        dsto[i] = (uint32_t)(frow + i * 16) * 128u + (uint32_t)((fu ^ r7) << 4);

#define ISSUE_STAGE(st, kt) do {                                              \
    const uint32_t base = sbw + (uint32_t)(st) * 32768u;                      \
    const float* pa = Ag + (size_t)(kt) * BK;                                 \
    const float* pb = Bg + (size_t)(kt) * BK;                                 \
    _Pragma("unroll")                                                         \
    for (int i = 0; i < 8; ++i) {                                             \
        asm volatile("cp.async.cg.shared.global [%0], [%1], 16;"              \
            :: "r"(base + dsto[i]), "l"(pa + i * rstep) : "memory");          \
        asm volatile("cp.async.cg.shared.global [%0], [%1], 16;"              \
            :: "r"(base + 16384u + dsto[i]), "l"(pb + i * rstep) : "memory"); \
    }                                                                         \
    asm volatile("cp.async.commit_group;" ::: "memory");                      \
  } while (0)

    // ---- fragment smem word offsets (swizzle term reduces to u^g)
    uint32_t arow[4], brow[8];
    #pragma unroll
    for (int mt = 0; mt < 4; ++mt)
        arow[mt] = (uint32_t)(warp_m * 64 + mt * 16 + g) * 32u;
    #pragma unroll
    for (int nt = 0; nt < 8; ++nt)
        brow[nt] = (uint32_t)(warp_n * 64 + nt * 8 + g) * 32u;

    float acc[4][8][4];
    #pragma unroll
    for (int mt = 0; mt < 4; ++mt)
        #pragma unroll
        for (int nt = 0; nt < 8; ++nt)
            #pragma unroll
            for (int r = 0; r < 4; ++r) acc[mt][nt][r] = 0.f;

    const int KT = K / BK;   // 64

    ISSUE_STAGE(0, 0);
    ISSUE_STAGE(1, 1);

    for (int kt = 0; kt < KT; ++kt) {
        asm volatile("cp.async.wait_group 1;" ::: "memory");
        __syncthreads();
        if (kt + 2 < KT) ISSUE_STAGE((kt + 2) % STAGES, kt + 2);

        const uint32_t* sA = smp + (kt % STAGES) * 8192;
        const uint32_t* sB = sA + 4096;

        #pragma unroll
        for (int kc = 0; kc < 4; ++kc) {
            const uint32_t x0 = (uint32_t)(((2 * kc)     ^ g) * 4 + c);
            const uint32_t x1 = (uint32_t)(((2 * kc + 1) ^ g) * 4 + c);
            uint32_t af[4][4], bf[8][2];
            #pragma unroll
            for (int mt = 0; mt < 4; ++mt) {
                af[mt][0] = sA[arow[mt] + x0];
                af[mt][1] = sA[arow[mt] + 256 + x0];
                af[mt][2] = sA[arow[mt] + x1];
                af[mt][3] = sA[arow[mt] + 256 + x1];
            }
            #pragma unroll
            for (int nt = 0; nt < 8; ++nt) {
                bf[nt][0] = sB[brow[nt] + x0];
                bf[nt][1] = sB[brow[nt] + x1];
            }
            #pragma unroll
            for (int mt = 0; mt < 4; ++mt)
                #pragma unroll
                for (int nt = 0; nt < 8; ++nt) {
                    asm volatile(
                        "mma.sync.aligned.m16n8k8.row.col.f32.tf32.tf32.f32 "
                        "{%0,%1,%2,%3}, {%4,%5,%6,%7}, {%8,%9}, {%0,%1,%2,%3};"
                        : "+f"(acc[mt][nt][0]), "+f"(acc[mt][nt][1]),
                          "+f"(acc[mt][nt][2]), "+f"(acc[mt][nt][3])
                        : "r"(af[mt][0]), "r"(af[mt][1]),
                          "r"(af[mt][2]), "r"(af[mt][3]),
                          "r"(bf[nt][0]), "r"(bf[nt][1]));
                }
        }
    }
#undef ISSUE_STAGE

    // epilogue: c0:(g,2c) c1:(g,2c+1) c2:(g+8,2c) c3:(g+8,2c+1)
    #pragma unroll
    for (int mt = 0; mt < 4; ++mt) {
        const int r0 = m0 + warp_m * 64 + mt * 16 + g;
        const int r1 = r0 + 8;
        float* p0 = C + (size_t)r0 * Nn;
        float* p1 = C + (size_t)r1 * Nn;
        #pragma unroll
        for (int nt = 0; nt < 8; ++nt) {
            const int col = n0 + warp_n * 64 + nt * 8 + c * 2;
            float2 v0 = make_float2(acc[mt][nt][0], acc[mt][nt][1]);
            float2 v1 = make_float2(acc[mt][nt][2], acc[mt][nt][3]);
            if (FUSE_SKIP) {
                const float2 x0 = *(const float2*)(sx + (size_t)r0 * Nn + col);
                const float2 x1 = *(const float2*)(sx + (size_t)r1 * Nn + col);
                const float2 dd = *(const float2*)(sd + col);
                v0.x = fmaf(x0.x, dd.x, v0.x);
                v0.y = fmaf(x0.y, dd.y, v0.y);
                v1.x = fmaf(x1.x, dd.x, v1.x);
                v1.y = fmaf(x1.y, dd.y, v1.y);
            }
            *(float2*)(p0 + col) = v0;
            *(float2*)(p1 + col) = v1;
        }
    }
}

// ---------------------------------------------------------------------------
// Chunked diagonal scan: h_t = lam * h_{t-1} + b_t
// ---------------------------------------------------------------------------
__global__ void scan_chunk_reduce(const float* __restrict__ Bmat,
                                  const float* __restrict__ lam,
                                  float* __restrict__ E)
{
    const int n = blockIdx.x * blockDim.x + threadIdx.x;
    const int cc = blockIdx.y;
    const float l = lam[n];
    const float* p = Bmat + (size_t)cc * CHUNK * DIM_N + n;
    float h = 0.f;
    #pragma unroll 4
    for (int t = 0; t < CHUNK; ++t)
        h = fmaf(l, h, p[(size_t)t * DIM_N]);
    E[(size_t)cc * DIM_N + n] = h;
}

__global__ void scan_carry(const float* __restrict__ lam,
                           const float* __restrict__ E,
                           float* __restrict__ Cin)
{
    const int n = blockIdx.x * blockDim.x + threadIdx.x;
    const float l = lam[n];
    float lT = l;
    #pragma unroll
    for (int i = 0; i < 7; ++i) lT *= lT;   // l^128
    float cin = 0.f;
    for (int cc = 0; cc < NCHUNK; ++cc) {
        Cin[(size_t)cc * DIM_N + n] = cin;
        cin = fmaf(lT, cin, E[(size_t)cc * DIM_N + n]);
    }
}

// writes tf32-rounded H (consumed only as GEMM2's A operand)
__global__ void scan_apply(const float* __restrict__ Bmat,
                           const float* __restrict__ lam,
                           const float* __restrict__ Cin,
                           float* __restrict__ H)
{
    const int n = blockIdx.x * blockDim.x + threadIdx.x;
    const int cc = blockIdx.y;
    const float l = lam[n];
    const float* p = Bmat + (size_t)cc * CHUNK * DIM_N + n;
    float*       q = H    + (size_t)cc * CHUNK * DIM_N + n;
    float h = Cin[(size_t)cc * DIM_N + n];
    #pragma unroll 4
    for (int t = 0; t < CHUNK; ++t) {
        h = fmaf(l, h, p[(size_t)t * DIM_N]);
        q[(size_t)t * DIM_N] = __uint_as_float(f2tf32(h));
    }
}

// ---------------------------------------------------------------------------
extern "C" void kernel_launch(void* const* d_in, const int* in_sizes, int n_in,
                              void* d_out, int out_size)
{
    const float* xs     = (const float*)d_in[0];   // [SEQ_L, DIM_I]
    const float* lam    = (const float*)d_in[1];   // [DIM_N]
    const float* w_in   = (const float*)d_in[2];   // [DIM_N, DIM_I]
    const float* c_out  = (const float*)d_in[3];   // [DIM_I, DIM_N]
    const float* d_skip = (const float*)d_in[4];   // [DIM_I]
    float* out = (float*)d_out;                    // [SEQ_L, DIM_I]

    float *Bp, *Hp, *Ep, *Cp, *Xc, *Wc, *Cc;
    cudaGetSymbolAddress((void**)&Bp, g_B);
    cudaGetSymbolAddress((void**)&Hp, g_H);
    cudaGetSymbolAddress((void**)&Ep, g_E);
    cudaGetSymbolAddress((void**)&Cp, g_Cin);
    cudaGetSymbolAddress((void**)&Xc, g_Xc);
    cudaGetSymbolAddress((void**)&Wc, g_Wc);
    cudaGetSymbolAddress((void**)&Cc, g_Cc);

    const int SMEM_DYN = 3 * 32768;   // 96 KB
    cudaFuncSetAttribute(gemm_mma<false>,
        cudaFuncAttributeMaxDynamicSharedMemorySize, SMEM_DYN);
    cudaFuncSetAttribute(gemm_mma<true>,
        cudaFuncAttributeMaxDynamicSharedMemorySize, SMEM_DYN);

    // Pre-round operands to tf32
    {
        int n4 = SEQ_L * DIM_I / 4;
        cvt_tf32_kernel<<<n4 / 256, 256>>>((const float4*)xs, (float4*)Xc, n4);
        n4 = DIM_N * DIM_I / 4;
        cvt_tf32_kernel<<<n4 / 256, 256>>>((const float4*)w_in, (float4*)Wc, n4);
        n4 = DIM_I * DIM_N / 4;
        cvt_tf32_kernel<<<n4 / 256, 256>>>((const float4*)c_out, (float4*)Cc, n4);
    }

    // GEMM1: B = xs @ w_in^T
    dim3 g1(DIM_N / 128, SEQ_L / 128);
    gemm_mma<false><<<g1, 128, SMEM_DYN>>>(Xc, Wc, Bp, nullptr, nullptr,
                                           SEQ_L, DIM_N, DIM_I);

    // Scan: H = assoc_scan(lam, B)
    dim3 gs(DIM_N / 256, NCHUNK);
    scan_chunk_reduce<<<gs, 256>>>(Bp, lam, Ep);
    scan_carry<<<DIM_N / 256, 256>>>(lam, Ep, Cp);
    scan_apply<<<gs, 256>>>(Bp, lam, Cp, Hp);

    // GEMM2: out = H @ c_out^T + xs * d_skip
    dim3 g2(DIM_I / 128, SEQ_L / 128);
    gemm_mma<true><<<g2, 128, SMEM_DYN>>>(Hp, Cc, out, xs, d_skip,
                                          SEQ_L, DIM_I, DIM_N);
}